// round 15
// baseline (speedup 1.0000x reference)
#include <cuda_runtime.h>
#include <math.h>

#define BB   2
#define LL   2048
#define DD   1024
#define NHH  16
#define KVHH 8
#define DHH  64

// ---------------- scratch (device globals; no allocation allowed) ----------
__device__ float g_q[(size_t)BB * NHH * LL * DHH];      // 16 MB  [b][h][l][dh]
__device__ float g_k[(size_t)BB * KVHH * LL * DHH];     // 8 MB   [b][kh][l][dh]
__device__ float g_v[(size_t)BB * KVHH * LL * DHH];     // 8 MB   [b][kh][l][dh]
__device__ float g_attn[(size_t)BB * LL * NHH * DHH];   // 16 MB  [b][l][h*64+dh]

// fused-attention smem layout (bytes)
#define SROW    2052                       // padded row stride for S (floats)
#define OFF_S   0                          // S[16][2052]            131328 B
#define OFF_Q   131328                     // Qs[16][68]               4352 B
#define OFF_T   135680                     // K/V tile [128][68]      34816 B
#define OFF_H   170496                     // hist [8][256]            8192 B
#define SMEM_TOTAL 178688

// ---------------------------------------------------------------------------
// Tiled fp32 GEMM, 128x128 tile, 8x8 microtile, k-chunk 16.
// Ascending k, chunk flush every 8 chunks (=128 k): bitwise-identical
// accumulation to the previous (passing) kernel.
// ---------------------------------------------------------------------------
__global__ __launch_bounds__(256) void gemm_plain(
    const float* __restrict__ Aext, const float* __restrict__ Bm,
    float* __restrict__ Cext, int M, int N, int K,
    int a_sel, int dst, int H)
{
    __shared__ float As[16][128];
    __shared__ float Bs[16][128];
    const float* A = a_sel ? g_attn : Aext;

    int t  = threadIdx.x;
    int tx = t & 15, ty = t >> 4;
    int rowBase = blockIdx.y * 128;
    int colBase = blockIdx.x * 128;

    int aRow = t >> 1;
    int aK8  = (t & 1) * 8;
    int bK   = t >> 5;
    int bC4  = (t & 31) * 4;

    float acc[8][8] = {};
    float loc[8][8] = {};
    int chunk = 0;

    for (int k0 = 0; k0 < K; k0 += 16) {
        const float* ap = &A[(size_t)(rowBase + aRow) * K + k0 + aK8];
        float4 av0 = *(const float4*)ap;
        float4 av1 = *(const float4*)(ap + 4);
        As[aK8 + 0][aRow] = av0.x;
        As[aK8 + 1][aRow] = av0.y;
        As[aK8 + 2][aRow] = av0.z;
        As[aK8 + 3][aRow] = av0.w;
        As[aK8 + 4][aRow] = av1.x;
        As[aK8 + 5][aRow] = av1.y;
        As[aK8 + 6][aRow] = av1.z;
        As[aK8 + 7][aRow] = av1.w;
        float4 bv0 = *(const float4*)&Bm[(size_t)(k0 + bK) * N + colBase + bC4];
        float4 bv1 = *(const float4*)&Bm[(size_t)(k0 + bK + 8) * N + colBase + bC4];
        *(float4*)&Bs[bK][bC4]     = bv0;
        *(float4*)&Bs[bK + 8][bC4] = bv1;
        __syncthreads();
#pragma unroll
        for (int k = 0; k < 16; ++k) {
            float4 a0 = *(const float4*)&As[k][ty * 8];
            float4 a1 = *(const float4*)&As[k][ty * 8 + 4];
            float4 b0 = *(const float4*)&Bs[k][tx * 8];
            float4 b1 = *(const float4*)&Bs[k][tx * 8 + 4];
            float ar[8] = {a0.x, a0.y, a0.z, a0.w, a1.x, a1.y, a1.z, a1.w};
            float br[8] = {b0.x, b0.y, b0.z, b0.w, b1.x, b1.y, b1.z, b1.w};
#pragma unroll
            for (int i = 0; i < 8; ++i)
#pragma unroll
                for (int j = 0; j < 8; ++j)
                    loc[i][j] = fmaf(ar[i], br[j], loc[i][j]);
        }
        __syncthreads();
        if ((++chunk & 7) == 0) {
#pragma unroll
            for (int i = 0; i < 8; ++i)
#pragma unroll
                for (int j = 0; j < 8; ++j) {
                    acc[i][j] += loc[i][j];
                    loc[i][j] = 0.0f;
                }
        }
    }
#pragma unroll
    for (int i = 0; i < 8; ++i)
#pragma unroll
        for (int j = 0; j < 8; ++j)
            acc[i][j] += loc[i][j];

#pragma unroll
    for (int i = 0; i < 8; ++i) {
        int r = rowBase + ty * 8 + i;
#pragma unroll
        for (int jj = 0; jj < 2; ++jj) {
            int c = colBase + tx * 8 + jj * 4;
            float4 v = make_float4(acc[i][jj * 4 + 0], acc[i][jj * 4 + 1],
                                   acc[i][jj * 4 + 2], acc[i][jj * 4 + 3]);
            if (dst < 0) {
                *(float4*)&Cext[(size_t)r * N + c] = v;
            } else {
                int b = r / LL, l = r % LL;
                int h = c >> 6, dh = c & 63;
                size_t idx = (((size_t)(b * H + h)) * LL + l) * 64 + dh;
                float* dp = (dst == 0) ? g_q : (dst == 1 ? g_k : g_v);
                *(float4*)&dp[idx] = v;
            }
        }
    }
}

// ---------------------------------------------------------------------------
// Fused RoPE (unchanged; reference-bit-exact rounding chain).
// ---------------------------------------------------------------------------
__global__ __launch_bounds__(256) void rope_fused(const int* __restrict__ pos)
{
    __shared__ float cs[32], sn[32];
    int bl = blockIdx.x;
    int b = bl / LL, l = bl % LL;
    int t = threadIdx.x;

    if (t < 32) {
        float e    = (float)(2 * t) / 64.0f;
        float p    = (float)pow(10000.0, (double)e);
        float invf = __fdiv_rn(1.0f, p);
        float f    = __fmul_rn((float)pos[bl], invf);
        double fd  = (double)f;
        cs[t] = (float)cos(fd);
        sn[t] = (float)sin(fd);
    }
    __syncthreads();

    for (int w = t; w < (NHH + KVHH) * 32; w += 256) {
        int i  = w & 31;
        int hh = w >> 5;
        float* x;
        if (hh < NHH)
            x = g_q + (((size_t)(b * NHH + hh)) * LL + l) * 64;
        else
            x = g_k + (((size_t)(b * KVHH + (hh - NHH))) * LL + l) * 64;
        float c = cs[i], s = sn[i];
        float x0 = x[i], x1 = x[i + 32];
        x[i]      = __fsub_rn(__fmul_rn(x0, c), __fmul_rn(x1, s));
        x[i + 32] = __fadd_rn(__fmul_rn(x1, c), __fmul_rn(x0, s));
    }
}

// ---------------------------------------------------------------------------
// FUSED attention: scores + exact top-1024 + softmax + P@V for one head and
// one 16-query strip, all in shared memory. Scores are the same ascending-d
// fmaf chains (x0.125f) as the previous passing kernel -> identical bits ->
// identical radix selection. P@V accumulates ascending k.
// grid (L/16, B*NH), 256 threads, SMEM_TOTAL dynamic smem.
// ---------------------------------------------------------------------------
__global__ __launch_bounds__(256) void fused_attn()
{
    extern __shared__ char smem[];
    float* S    = (float*)(smem + OFF_S);    // [16][SROW]
    float* Qs   = (float*)(smem + OFF_Q);    // [16][68]
    float* T    = (float*)(smem + OFF_T);    // K/V tile [128][68]
    int*   HIST = (int*)  (smem + OFF_H);    // [8][256]

    const int t    = threadIdx.x;
    const int lane = t & 31, w = t >> 5;
    const int qb   = blockIdx.x * 16;
    const int z    = blockIdx.y;             // b*NH + h
    const int b    = z / NHH, h = z % NHH;

    const float* Qg = g_q + ((size_t)z * LL + qb) * 64;
    const float* Kg = g_k + ((size_t)(b * KVHH + (h >> 1)) * LL) * 64;
    const float* Vg = g_v + ((size_t)(b * KVHH + (h >> 1)) * LL) * 64;

    // ---- load Q strip [16][64] -> Qs[16][68] ----
    {
        int row = t >> 4, d4 = (t & 15) * 4;
        *(float4*)&Qs[row * 68 + d4] = *(const float4*)&Qg[row * 64 + d4];
    }

    // ================= phase A: scores =================
    const int ty = t >> 6;          // rows 4ty..4ty+3
    const int tx = t & 63;          // keys 2tx, 2tx+1

    for (int kt = 0; kt < 16; ++kt) {
        __syncthreads();
#pragma unroll
        for (int i = 0; i < 8; ++i) {               // K tile -> T[key][68]
            int lin = t + 256 * i;
            int key = lin >> 4, d4 = (lin & 15) * 4;
            *(float4*)&T[key * 68 + d4] =
                *(const float4*)&Kg[(size_t)(kt * 128 + key) * 64 + d4];
        }
        __syncthreads();

        float acc[4][2] = {};
#pragma unroll
        for (int d0 = 0; d0 < 64; d0 += 4) {
            float4 k0 = *(const float4*)&T[(2 * tx    ) * 68 + d0];
            float4 k1 = *(const float4*)&T[(2 * tx + 1) * 68 + d0];
#pragma unroll
            for (int i = 0; i < 4; ++i) {
                float4 qv = *(const float4*)&Qs[(4 * ty + i) * 68 + d0];
                acc[i][0] = fmaf(qv.x, k0.x, acc[i][0]);
                acc[i][0] = fmaf(qv.y, k0.y, acc[i][0]);
                acc[i][0] = fmaf(qv.z, k0.z, acc[i][0]);
                acc[i][0] = fmaf(qv.w, k0.w, acc[i][0]);
                acc[i][1] = fmaf(qv.x, k1.x, acc[i][1]);
                acc[i][1] = fmaf(qv.y, k1.y, acc[i][1]);
                acc[i][1] = fmaf(qv.z, k1.z, acc[i][1]);
                acc[i][1] = fmaf(qv.w, k1.w, acc[i][1]);
            }
        }
#pragma unroll
        for (int i = 0; i < 4; ++i) {
            S[(4 * ty + i) * SROW + kt * 128 + 2 * tx    ] = acc[i][0] * 0.125f;
            S[(4 * ty + i) * SROW + kt * 128 + 2 * tx + 1] = acc[i][1] * 0.125f;
        }
    }
    __syncthreads();

    // ======== phase B: per-row top-1024 + softmax (warp per row) ========
    int* histw = HIST + w * 256;
    for (int rr = 0; rr < 2; ++rr) {
        int row = 2 * w + rr;
        float* srow = S + row * SROW;

        unsigned prefix = 0, prefmask = 0;
        int want = 1024;
        for (int pass = 0; pass < 4; ++pass) {
            int shift = 24 - pass * 8;
#pragma unroll
            for (int i = 0; i < 8; ++i) histw[lane + 32 * i] = 0;
            __syncwarp();
            for (int i = 0; i < 64; ++i) {
                float sv = srow[lane + 32 * i];
                unsigned bts = __float_as_uint(sv);
                unsigned uv = (bts & 0x80000000u) ? ~bts : (bts | 0x80000000u);
                if ((uv & prefmask) == prefix)
                    atomicAdd(&histw[(uv >> shift) & 255], 1);
            }
            __syncwarp();
            int hv[8], Sl = 0;
#pragma unroll
            for (int j = 0; j < 8; ++j) { hv[j] = histw[8 * lane + j]; Sl += hv[j]; }
            int suf = Sl;
#pragma unroll
            for (int o = 1; o < 32; o <<= 1) {
                int vv = __shfl_down_sync(0xFFFFFFFFu, suf, o);
                if (lane + o < 32) suf += vv;
            }
            int run = suf - Sl;        // suffix-exclusive of this lane's top bin
            int seld = -1, selw = 0;
#pragma unroll
            for (int j = 7; j >= 0; --j) {
                int incl = run + hv[j];
                if (run < want && want <= incl) { seld = 8 * lane + j; selw = want - run; }
                run = incl;
            }
            unsigned mball = __ballot_sync(0xFFFFFFFFu, seld >= 0);
            int src = __ffs(mball) - 1;
            seld = __shfl_sync(0xFFFFFFFFu, seld, src);
            selw = __shfl_sync(0xFFFFFFFFu, selw, src);
            prefix |= ((unsigned)seld) << shift;
            prefmask |= 0xFFu << shift;
            want = selw;
        }
        unsigned uth = prefix;

        float mval = -INFINITY;
        for (int i = 0; i < 64; ++i) mval = fmaxf(mval, srow[lane + 32 * i]);
#pragma unroll
        for (int o = 16; o > 0; o >>= 1)
            mval = fmaxf(mval, __shfl_xor_sync(0xFFFFFFFFu, mval, o));

        float sum = 0.0f;
        for (int i = 0; i < 64; ++i) {
            float sv = srow[lane + 32 * i];
            unsigned bts = __float_as_uint(sv);
            unsigned uv = (bts & 0x80000000u) ? ~bts : (bts | 0x80000000u);
            float e = (uv >= uth) ? __expf(sv - mval) : 0.0f;
            srow[lane + 32 * i] = e;
            sum += e;
        }
#pragma unroll
        for (int o = 16; o > 0; o >>= 1)
            sum += __shfl_xor_sync(0xFFFFFFFFu, sum, o);
        float inv = 1.0f / sum;
        for (int i = 0; i < 64; ++i) srow[lane + 32 * i] *= inv;
    }

    // ================= phase C: O = P @ V =================
    // warp w -> cols 8w..8w+7; lane: col = 8w + (lane&7), rows rg+4i (rg=lane>>3)
    const int colw = w * 8 + (lane & 7);
    const int rg   = lane >> 3;
    float oacc[4] = {0.f, 0.f, 0.f, 0.f};

    for (int kt = 0; kt < 16; ++kt) {
        __syncthreads();
#pragma unroll
        for (int i = 0; i < 8; ++i) {               // V tile -> T[key][68]
            int lin = t + 256 * i;
            int key = lin >> 4, d4 = (lin & 15) * 4;
            *(float4*)&T[key * 68 + d4] =
                *(const float4*)&Vg[(size_t)(kt * 128 + key) * 64 + d4];
        }
        __syncthreads();
#pragma unroll 8
        for (int k0 = 0; k0 < 128; k0 += 4) {
            float v0 = T[(k0 + 0) * 68 + colw];
            float v1 = T[(k0 + 1) * 68 + colw];
            float v2 = T[(k0 + 2) * 68 + colw];
            float v3 = T[(k0 + 3) * 68 + colw];
#pragma unroll
            for (int i = 0; i < 4; ++i) {
                float4 pv = *(const float4*)&S[(rg + 4 * i) * SROW + kt * 128 + k0];
                oacc[i] = fmaf(pv.x, v0, oacc[i]);
                oacc[i] = fmaf(pv.y, v1, oacc[i]);
                oacc[i] = fmaf(pv.z, v2, oacc[i]);
                oacc[i] = fmaf(pv.w, v3, oacc[i]);
            }
        }
    }

#pragma unroll
    for (int i = 0; i < 4; ++i)
        g_attn[((size_t)(b * LL + qb + rg + 4 * i)) * (NHH * DHH) + h * 64 + colw] = oacc[i];
}

// ---------------------------------------------------------------------------
extern "C" void kernel_launch(void* const* d_in, const int* in_sizes, int n_in,
                              void* d_out, int out_size)
{
    const float* hs  = (const float*)d_in[0];  // [B,L,D]
    const float* wq  = (const float*)d_in[1];  // [D, NH*DH]
    const float* wk  = (const float*)d_in[2];  // [D, KVH*DH]
    const float* wv  = (const float*)d_in[3];  // [D, KVH*DH]
    const float* wo  = (const float*)d_in[4];  // [NH*DH, D]
    const int*   pos = (const int*)d_in[5];    // [B,L]
    float* out = (float*)d_out;                // [B,L,D]

    cudaFuncSetAttribute(fused_attn,
                         cudaFuncAttributeMaxDynamicSharedMemorySize, SMEM_TOTAL);

    dim3 blk(256);

    // QKV projections (head-split epilogue)
    gemm_plain<<<dim3((NHH * DHH) / 128, (BB * LL) / 128), blk>>>(
        hs, wq, nullptr, BB * LL, NHH * DHH, DD, 0, 0, NHH);
    gemm_plain<<<dim3((KVHH * DHH) / 128, (BB * LL) / 128), blk>>>(
        hs, wk, nullptr, BB * LL, KVHH * DHH, DD, 0, 1, KVHH);
    gemm_plain<<<dim3((KVHH * DHH) / 128, (BB * LL) / 128), blk>>>(
        hs, wv, nullptr, BB * LL, KVHH * DHH, DD, 0, 2, KVHH);

    // RoPE (q + k in one fused launch)
    rope_fused<<<BB * LL, 256>>>(pos);

    // Fused scores + top-k + softmax + P@V
    fused_attn<<<dim3(LL / 16, BB * NHH), blk, SMEM_TOTAL>>>();

    // Output projection
    gemm_plain<<<dim3(DD / 128, (BB * LL) / 128), blk>>>(
        nullptr, wo, out, BB * LL, DD, NHH * DHH, 1, -1, 0);
}

// round 16
// speedup vs baseline: 1.0004x; 1.0004x over previous
#include <cuda_runtime.h>
#include <math.h>

#define BB   2
#define LL   2048
#define DD   1024
#define NHH  16
#define KVHH 8
#define DHH  64

// ---------------- scratch (device globals; no allocation allowed) ----------
__device__ float g_q[(size_t)BB * NHH * LL * DHH];      // 16 MB  [b][h][l][dh]
__device__ float g_k[(size_t)BB * KVHH * LL * DHH];     // 8 MB   [b][kh][l][dh]
__device__ float g_v[(size_t)BB * KVHH * LL * DHH];     // 8 MB   [b][kh][l][dh]
__device__ float g_attn[(size_t)BB * LL * NHH * DHH];   // 16 MB  [b][l][h*64+dh]

// fused-attention smem layout (bytes)
#define SROW    2052                       // padded row stride for S (floats)
#define OFF_S   0                          // S[16][2052]            131328 B
#define OFF_Q   131328                     // Qs[16][68]               4352 B
#define OFF_T   135680                     // K/V tile [128][68]      34816 B
#define OFF_H   170496                     // hist [8][256]            8192 B
#define SMEM_TOTAL 178688

// ---------------------------------------------------------------------------
// Tiled fp32 GEMM, 128x128 tile, 8x8 microtile, k-chunk 16.
// Ascending k, chunk flush every 8 chunks (=128 k): bitwise-identical
// accumulation to the previous (passing) kernel.
// ---------------------------------------------------------------------------
__global__ __launch_bounds__(256) void gemm_plain(
    const float* __restrict__ Aext, const float* __restrict__ Bm,
    float* __restrict__ Cext, int M, int N, int K,
    int a_sel, int dst, int H)
{
    __shared__ float As[16][128];
    __shared__ float Bs[16][128];
    const float* A = a_sel ? g_attn : Aext;

    int t  = threadIdx.x;
    int tx = t & 15, ty = t >> 4;
    int rowBase = blockIdx.y * 128;
    int colBase = blockIdx.x * 128;

    int aRow = t >> 1;
    int aK8  = (t & 1) * 8;
    int bK   = t >> 5;
    int bC4  = (t & 31) * 4;

    float acc[8][8] = {};
    float loc[8][8] = {};
    int chunk = 0;

    for (int k0 = 0; k0 < K; k0 += 16) {
        const float* ap = &A[(size_t)(rowBase + aRow) * K + k0 + aK8];
        float4 av0 = *(const float4*)ap;
        float4 av1 = *(const float4*)(ap + 4);
        As[aK8 + 0][aRow] = av0.x;
        As[aK8 + 1][aRow] = av0.y;
        As[aK8 + 2][aRow] = av0.z;
        As[aK8 + 3][aRow] = av0.w;
        As[aK8 + 4][aRow] = av1.x;
        As[aK8 + 5][aRow] = av1.y;
        As[aK8 + 6][aRow] = av1.z;
        As[aK8 + 7][aRow] = av1.w;
        float4 bv0 = *(const float4*)&Bm[(size_t)(k0 + bK) * N + colBase + bC4];
        float4 bv1 = *(const float4*)&Bm[(size_t)(k0 + bK + 8) * N + colBase + bC4];
        *(float4*)&Bs[bK][bC4]     = bv0;
        *(float4*)&Bs[bK + 8][bC4] = bv1;
        __syncthreads();
#pragma unroll
        for (int k = 0; k < 16; ++k) {
            float4 a0 = *(const float4*)&As[k][ty * 8];
            float4 a1 = *(const float4*)&As[k][ty * 8 + 4];
            float4 b0 = *(const float4*)&Bs[k][tx * 8];
            float4 b1 = *(const float4*)&Bs[k][tx * 8 + 4];
            float ar[8] = {a0.x, a0.y, a0.z, a0.w, a1.x, a1.y, a1.z, a1.w};
            float br[8] = {b0.x, b0.y, b0.z, b0.w, b1.x, b1.y, b1.z, b1.w};
#pragma unroll
            for (int i = 0; i < 8; ++i)
#pragma unroll
                for (int j = 0; j < 8; ++j)
                    loc[i][j] = fmaf(ar[i], br[j], loc[i][j]);
        }
        __syncthreads();
        if ((++chunk & 7) == 0) {
#pragma unroll
            for (int i = 0; i < 8; ++i)
#pragma unroll
                for (int j = 0; j < 8; ++j) {
                    acc[i][j] += loc[i][j];
                    loc[i][j] = 0.0f;
                }
        }
    }
#pragma unroll
    for (int i = 0; i < 8; ++i)
#pragma unroll
        for (int j = 0; j < 8; ++j)
            acc[i][j] += loc[i][j];

#pragma unroll
    for (int i = 0; i < 8; ++i) {
        int r = rowBase + ty * 8 + i;
#pragma unroll
        for (int jj = 0; jj < 2; ++jj) {
            int c = colBase + tx * 8 + jj * 4;
            float4 v = make_float4(acc[i][jj * 4 + 0], acc[i][jj * 4 + 1],
                                   acc[i][jj * 4 + 2], acc[i][jj * 4 + 3]);
            if (dst < 0) {
                *(float4*)&Cext[(size_t)r * N + c] = v;
            } else {
                int b = r / LL, l = r % LL;
                int h = c >> 6, dh = c & 63;
                size_t idx = (((size_t)(b * H + h)) * LL + l) * 64 + dh;
                float* dp = (dst == 0) ? g_q : (dst == 1 ? g_k : g_v);
                *(float4*)&dp[idx] = v;
            }
        }
    }
}

// ---------------------------------------------------------------------------
// Fused RoPE (unchanged; reference-bit-exact rounding chain).
// ---------------------------------------------------------------------------
__global__ __launch_bounds__(256) void rope_fused(const int* __restrict__ pos)
{
    __shared__ float cs[32], sn[32];
    int bl = blockIdx.x;
    int b = bl / LL, l = bl % LL;
    int t = threadIdx.x;

    if (t < 32) {
        float e    = (float)(2 * t) / 64.0f;
        float p    = (float)pow(10000.0, (double)e);
        float invf = __fdiv_rn(1.0f, p);
        float f    = __fmul_rn((float)pos[bl], invf);
        double fd  = (double)f;
        cs[t] = (float)cos(fd);
        sn[t] = (float)sin(fd);
    }
    __syncthreads();

    for (int w = t; w < (NHH + KVHH) * 32; w += 256) {
        int i  = w & 31;
        int hh = w >> 5;
        float* x;
        if (hh < NHH)
            x = g_q + (((size_t)(b * NHH + hh)) * LL + l) * 64;
        else
            x = g_k + (((size_t)(b * KVHH + (hh - NHH))) * LL + l) * 64;
        float c = cs[i], s = sn[i];
        float x0 = x[i], x1 = x[i + 32];
        x[i]      = __fsub_rn(__fmul_rn(x0, c), __fmul_rn(x1, s));
        x[i + 32] = __fadd_rn(__fmul_rn(x1, c), __fmul_rn(x0, s));
    }
}

// ---------------------------------------------------------------------------
// FUSED attention: scores + exact top-1024 + softmax + P@V for one head and
// one 16-query strip, all in shared memory. Scores are the same ascending-d
// fmaf chains (x0.125f) as the previous passing kernel -> identical bits ->
// identical radix selection. P@V accumulates ascending k.
// grid (L/16, B*NH), 256 threads, SMEM_TOTAL dynamic smem.
// ---------------------------------------------------------------------------
__global__ __launch_bounds__(256) void fused_attn()
{
    extern __shared__ char smem[];
    float* S    = (float*)(smem + OFF_S);    // [16][SROW]
    float* Qs   = (float*)(smem + OFF_Q);    // [16][68]
    float* T    = (float*)(smem + OFF_T);    // K/V tile [128][68]
    int*   HIST = (int*)  (smem + OFF_H);    // [8][256]

    const int t    = threadIdx.x;
    const int lane = t & 31, w = t >> 5;
    const int qb   = blockIdx.x * 16;
    const int z    = blockIdx.y;             // b*NH + h
    const int b    = z / NHH, h = z % NHH;

    const float* Qg = g_q + ((size_t)z * LL + qb) * 64;
    const float* Kg = g_k + ((size_t)(b * KVHH + (h >> 1)) * LL) * 64;
    const float* Vg = g_v + ((size_t)(b * KVHH + (h >> 1)) * LL) * 64;

    // ---- load Q strip [16][64] -> Qs[16][68] ----
    {
        int row = t >> 4, d4 = (t & 15) * 4;
        *(float4*)&Qs[row * 68 + d4] = *(const float4*)&Qg[row * 64 + d4];
    }

    // ================= phase A: scores =================
    const int ty = t >> 6;          // rows 4ty..4ty+3
    const int tx = t & 63;          // keys 2tx, 2tx+1

    for (int kt = 0; kt < 16; ++kt) {
        __syncthreads();
#pragma unroll
        for (int i = 0; i < 8; ++i) {               // K tile -> T[key][68]
            int lin = t + 256 * i;
            int key = lin >> 4, d4 = (lin & 15) * 4;
            *(float4*)&T[key * 68 + d4] =
                *(const float4*)&Kg[(size_t)(kt * 128 + key) * 64 + d4];
        }
        __syncthreads();

        float acc[4][2] = {};
#pragma unroll
        for (int d0 = 0; d0 < 64; d0 += 4) {
            float4 k0 = *(const float4*)&T[(2 * tx    ) * 68 + d0];
            float4 k1 = *(const float4*)&T[(2 * tx + 1) * 68 + d0];
#pragma unroll
            for (int i = 0; i < 4; ++i) {
                float4 qv = *(const float4*)&Qs[(4 * ty + i) * 68 + d0];
                acc[i][0] = fmaf(qv.x, k0.x, acc[i][0]);
                acc[i][0] = fmaf(qv.y, k0.y, acc[i][0]);
                acc[i][0] = fmaf(qv.z, k0.z, acc[i][0]);
                acc[i][0] = fmaf(qv.w, k0.w, acc[i][0]);
                acc[i][1] = fmaf(qv.x, k1.x, acc[i][1]);
                acc[i][1] = fmaf(qv.y, k1.y, acc[i][1]);
                acc[i][1] = fmaf(qv.z, k1.z, acc[i][1]);
                acc[i][1] = fmaf(qv.w, k1.w, acc[i][1]);
            }
        }
#pragma unroll
        for (int i = 0; i < 4; ++i) {
            S[(4 * ty + i) * SROW + kt * 128 + 2 * tx    ] = acc[i][0] * 0.125f;
            S[(4 * ty + i) * SROW + kt * 128 + 2 * tx + 1] = acc[i][1] * 0.125f;
        }
    }
    __syncthreads();

    // ======== phase B: per-row top-1024 + softmax (warp per row) ========
    int* histw = HIST + w * 256;
    for (int rr = 0; rr < 2; ++rr) {
        int row = 2 * w + rr;
        float* srow = S + row * SROW;

        unsigned prefix = 0, prefmask = 0;
        int want = 1024;
        for (int pass = 0; pass < 4; ++pass) {
            int shift = 24 - pass * 8;
#pragma unroll
            for (int i = 0; i < 8; ++i) histw[lane + 32 * i] = 0;
            __syncwarp();
            for (int i = 0; i < 64; ++i) {
                float sv = srow[lane + 32 * i];
                unsigned bts = __float_as_uint(sv);
                unsigned uv = (bts & 0x80000000u) ? ~bts : (bts | 0x80000000u);
                if ((uv & prefmask) == prefix)
                    atomicAdd(&histw[(uv >> shift) & 255], 1);
            }
            __syncwarp();
            int hv[8], Sl = 0;
#pragma unroll
            for (int j = 0; j < 8; ++j) { hv[j] = histw[8 * lane + j]; Sl += hv[j]; }
            int suf = Sl;
#pragma unroll
            for (int o = 1; o < 32; o <<= 1) {
                int vv = __shfl_down_sync(0xFFFFFFFFu, suf, o);
                if (lane + o < 32) suf += vv;
            }
            int run = suf - Sl;        // suffix-exclusive of this lane's top bin
            int seld = -1, selw = 0;
#pragma unroll
            for (int j = 7; j >= 0; --j) {
                int incl = run + hv[j];
                if (run < want && want <= incl) { seld = 8 * lane + j; selw = want - run; }
                run = incl;
            }
            unsigned mball = __ballot_sync(0xFFFFFFFFu, seld >= 0);
            int src = __ffs(mball) - 1;
            seld = __shfl_sync(0xFFFFFFFFu, seld, src);
            selw = __shfl_sync(0xFFFFFFFFu, selw, src);
            prefix |= ((unsigned)seld) << shift;
            prefmask |= 0xFFu << shift;
            want = selw;
        }
        unsigned uth = prefix;

        float mval = -INFINITY;
        for (int i = 0; i < 64; ++i) mval = fmaxf(mval, srow[lane + 32 * i]);
#pragma unroll
        for (int o = 16; o > 0; o >>= 1)
            mval = fmaxf(mval, __shfl_xor_sync(0xFFFFFFFFu, mval, o));

        float sum = 0.0f;
        for (int i = 0; i < 64; ++i) {
            float sv = srow[lane + 32 * i];
            unsigned bts = __float_as_uint(sv);
            unsigned uv = (bts & 0x80000000u) ? ~bts : (bts | 0x80000000u);
            float e = (uv >= uth) ? __expf(sv - mval) : 0.0f;
            srow[lane + 32 * i] = e;
            sum += e;
        }
#pragma unroll
        for (int o = 16; o > 0; o >>= 1)
            sum += __shfl_xor_sync(0xFFFFFFFFu, sum, o);
        float inv = 1.0f / sum;
        for (int i = 0; i < 64; ++i) srow[lane + 32 * i] *= inv;
    }

    // ================= phase C: O = P @ V =================
    // warp w -> cols 8w..8w+7; lane: col = 8w + (lane&7), rows rg+4i (rg=lane>>3)
    const int colw = w * 8 + (lane & 7);
    const int rg   = lane >> 3;
    float oacc[4] = {0.f, 0.f, 0.f, 0.f};

    for (int kt = 0; kt < 16; ++kt) {
        __syncthreads();
#pragma unroll
        for (int i = 0; i < 8; ++i) {               // V tile -> T[key][68]
            int lin = t + 256 * i;
            int key = lin >> 4, d4 = (lin & 15) * 4;
            *(float4*)&T[key * 68 + d4] =
                *(const float4*)&Vg[(size_t)(kt * 128 + key) * 64 + d4];
        }
        __syncthreads();
#pragma unroll 8
        for (int k0 = 0; k0 < 128; k0 += 4) {
            float v0 = T[(k0 + 0) * 68 + colw];
            float v1 = T[(k0 + 1) * 68 + colw];
            float v2 = T[(k0 + 2) * 68 + colw];
            float v3 = T[(k0 + 3) * 68 + colw];
#pragma unroll
            for (int i = 0; i < 4; ++i) {
                float4 pv = *(const float4*)&S[(rg + 4 * i) * SROW + kt * 128 + k0];
                oacc[i] = fmaf(pv.x, v0, oacc[i]);
                oacc[i] = fmaf(pv.y, v1, oacc[i]);
                oacc[i] = fmaf(pv.z, v2, oacc[i]);
                oacc[i] = fmaf(pv.w, v3, oacc[i]);
            }
        }
    }

#pragma unroll
    for (int i = 0; i < 4; ++i)
        g_attn[((size_t)(b * LL + qb + rg + 4 * i)) * (NHH * DHH) + h * 64 + colw] = oacc[i];
}

// ---------------------------------------------------------------------------
extern "C" void kernel_launch(void* const* d_in, const int* in_sizes, int n_in,
                              void* d_out, int out_size)
{
    const float* hs  = (const float*)d_in[0];  // [B,L,D]
    const float* wq  = (const float*)d_in[1];  // [D, NH*DH]
    const float* wk  = (const float*)d_in[2];  // [D, KVH*DH]
    const float* wv  = (const float*)d_in[3];  // [D, KVH*DH]
    const float* wo  = (const float*)d_in[4];  // [NH*DH, D]
    const int*   pos = (const int*)d_in[5];    // [B,L]
    float* out = (float*)d_out;                // [B,L,D]

    cudaFuncSetAttribute(fused_attn,
                         cudaFuncAttributeMaxDynamicSharedMemorySize, SMEM_TOTAL);

    dim3 blk(256);

    // QKV projections (head-split epilogue)
    gemm_plain<<<dim3((NHH * DHH) / 128, (BB * LL) / 128), blk>>>(
        hs, wq, nullptr, BB * LL, NHH * DHH, DD, 0, 0, NHH);
    gemm_plain<<<dim3((KVHH * DHH) / 128, (BB * LL) / 128), blk>>>(
        hs, wk, nullptr, BB * LL, KVHH * DHH, DD, 0, 1, KVHH);
    gemm_plain<<<dim3((KVHH * DHH) / 128, (BB * LL) / 128), blk>>>(
        hs, wv, nullptr, BB * LL, KVHH * DHH, DD, 0, 2, KVHH);

    // RoPE (q + k in one fused launch)
    rope_fused<<<BB * LL, 256>>>(pos);

    // Fused scores + top-k + softmax + P@V
    fused_attn<<<dim3(LL / 16, BB * NHH), blk, SMEM_TOTAL>>>();

    // Output projection
    gemm_plain<<<dim3(DD / 128, (BB * LL) / 128), blk>>>(
        nullptr, wo, out, BB * LL, DD, NHH * DHH, 1, -1, 0);
}